// round 13
// baseline (speedup 1.0000x reference)
#include <cuda_runtime.h>
#include <math.h>

#define BATCH 128
#define HDIM 512
#define WDIM 512
#define HW (HDIM*WDIM)            // 262144
#define GRID 296                   // = 148 SMs x 2 CTA slots: one full wave
#define NT 512
#define TOT4 (BATCH*HW/4)          // 8388608 float4s
#define QF (TOT4/GRID)             // 28339
#define RF (TOT4 - QF*GRID)        // 264 blocks get one extra float4
#define NVFULL (QF/NT)             // 55 uniform iterations
#define B4 (HW/4)                  // 65536 float4s per batch
#define NEGINF (-3.402823466e+38f)
#define IDENT_I 0x7FFFFFFF

// Scratch (device globals; no allocations allowed). 2 slots per block.
#define NSLOT (2*GRID)
__device__ float g_sum[NSLOT];
__device__ float g_gfk[NSLOT]; __device__ int g_gfi[NSLOT];
__device__ float g_g1u[NSLOT]; __device__ int g_g1i[NSLOT]; __device__ float g_g1c[NSLOT];
__device__ float g_g2u[NSLOT]; __device__ int g_g2i[NSLOT]; __device__ float g_g2c[NSLOT];
__device__ int   g_sbatch[NSLOT];
__device__ unsigned int g_ctr;     // zero-init; last block resets each launch

__device__ __forceinline__ bool better(float s, int i, float s2, int i2) {
    return s > s2 || (s == s2 && i < i2);
}

__device__ __forceinline__ int blk_start(int k) { return k*QF + min(k, RF); }

// -ln(u): poly in t=1-u where argmax contenders live (rel err < 1e-8 for
// t < 1/16), MUFU lg2 elsewhere (non-contenders; their error is harmless).
__device__ __forceinline__ float neg_ln(float u) {
    u = fmaxf(u, 1e-12f);            // reference clip (upper clip no-op in fp32)
    float t = 1.0f - u;
    float wp = t*(1.0f + t*(0.5f + t*(0.33333334f + t*(0.25f +
               t*(0.2f + t*(0.16666667f + t*0.14285715f))))));
    float wm = __log2f(u) * -0.69314718f;
    return (t < 0.0625f) ? wp : wm;
}

// block tree-reduction over one accumulator set
__device__ void reduce_set(float* s_sum, float* s_fk, int* s_fi,
                           float* s_b1u, int* s_b1i, float* s_b1c,
                           float* s_b2u, int* s_b2i, float* s_b2c, int t) {
    for (int o = NT/2; o > 0; o >>= 1) {
        if (t < o) {
            s_sum[t] += s_sum[t + o];
            if (better(s_fk[t+o], s_fi[t+o], s_fk[t], s_fi[t])) {
                s_fk[t] = s_fk[t+o]; s_fi[t] = s_fi[t+o];
            }
            float b1 = s_b1u[t+o]; int b1i = s_b1i[t+o]; float b1c = s_b1c[t+o];
            float b2 = s_b2u[t+o]; int b2i = s_b2i[t+o]; float b2c = s_b2c[t+o];
            float a1 = s_b1u[t];   int a1i = s_b1i[t];   float a1c = s_b1c[t];
            if (better(b1, b1i, a1, a1i)) {
                s_b1u[t] = b1; s_b1i[t] = b1i; s_b1c[t] = b1c;
                if (better(a1, a1i, b2, b2i)) { s_b2u[t] = a1; s_b2i[t] = a1i; s_b2c[t] = a1c; }
                else                          { s_b2u[t] = b2; s_b2i[t] = b2i; s_b2c[t] = b2c; }
            } else {
                if (better(b1, b1i, s_b2u[t], s_b2i[t])) { s_b2u[t] = b1; s_b2i[t] = b1i; s_b2c[t] = b1c; }
            }
        }
        __syncthreads();
    }
}

__global__ void __launch_bounds__(NT, 2)
k_all(const float* __restrict__ x, const float* __restrict__ ufg,
      const float* __restrict__ ubg, float* __restrict__ out) {
    int blk = blockIdx.x;
    int s4 = blk_start(blk);
    int n4 = QF + (blk < RF ? 1 : 0);
    const float4* cam = reinterpret_cast<const float4*>(x) + s4;
    const float4* uf  = reinterpret_cast<const float4*>(ufg) + s4;
    const float4* ub  = reinterpret_cast<const float4*>(ubg) + s4;
    float4* op = reinterpret_cast<float4*>(out) + s4;
    int t = threadIdx.x;
    int batchA = s4 >> 16;
    int batchB = (s4 + n4 - 1) >> 16;
    int cb = batchA;

    __shared__ float sAs[NT], sAfk[NT]; __shared__ int sAfi[NT];
    __shared__ float sA1u[NT]; __shared__ int sA1i[NT]; __shared__ float sA1c[NT];
    __shared__ float sA2u[NT]; __shared__ int sA2i[NT]; __shared__ float sA2c[NT];
    __shared__ float sBs[NT], sBfk[NT]; __shared__ int sBfi[NT];
    __shared__ float sB1u[NT]; __shared__ int sB1i[NT]; __shared__ float sB1c[NT];
    __shared__ float sB2u[NT]; __shared__ int sB2i[NT]; __shared__ float sB2c[NT];

    // identity A slot (used only if this thread never flushes into it)
    sAs[t] = 0.f; sAfk[t] = NEGINF; sAfi[t] = IDENT_I;
    sA1u[t] = -1.f; sA1i[t] = IDENT_I; sA1c[t] = 0.f;
    sA2u[t] = -2.f; sA2i[t] = IDENT_I; sA2c[t] = 0.f;
    sB2u[t] = -2.f; sB2i[t] = IDENT_I; sB2c[t] = 0.f;

    float sum = 0.f;
    float fk = NEGINF; int fi = IDENT_I;
    float bu = -1.f;   int bi = IDENT_I; float bc = 0.f;
    const float4 fill = make_float4(-255.f, -255.f, -255.f, -255.f);

#define FLUSH_A() do { \
        sAs[t] = sum; sAfk[t] = fk; sAfi[t] = fi; \
        sA1u[t] = bu; sA1i[t] = bi; sA1c[t] = bc; \
        sum = 0.f; fk = NEGINF; fi = IDENT_I; \
        bu = -1.f; bi = IDENT_I; bc = 0.f; \
    } while (0)

#define PROC(vl, c, f, g) do { \
        int v = s4 + (vl); \
        int vb = v >> 16; \
        if (vb != cb) { FLUSH_A(); cb = vb; } \
        int base = v * 4; \
        float cc[4] = {c.x, c.y, c.z, c.w}; \
        float ff[4] = {f.x, f.y, f.z, f.w}; \
        float gg[4] = {g.x, g.y, g.z, g.w}; \
        _Pragma("unroll") \
        for (int j = 0; j < 4; ++j) { \
            float ce = cc[j] + 1e-6f; \
            sum += ce; \
            float key = __fdividef(ce, neg_ln(ff[j])); \
            if (key > fk) { fk = key; fi = base + j; } \
            float u = gg[j]; \
            if (u > bu) { bu = u; bi = base + j; bc = cc[j]; } \
        } \
    } while (0)

    // software pipeline over 55 uniform iterations
    float4 c = cam[t];
    float4 f = uf[t];
    float4 g = ub[t];
    #pragma unroll 8
    for (int it = 0; it < NVFULL; ++it) {
        float4 cn, fn, gn;
        if (it + 1 < NVFULL) {
            int vn = (it+1)*NT + t;
            cn = cam[vn]; fn = uf[vn]; gn = ub[vn];
        }
        int vl = it*NT + t;
        op[vl] = fill;
        PROC(vl, c, f, g);
        if (it + 1 < NVFULL) { c = cn; f = fn; g = gn; }
    }
    // remainder (threads t < n4 - 55*NT)
    {
        int vl = NVFULL*NT + t;
        if (vl < n4) {
            float4 cr = cam[vl], fr = uf[vl], gr = ub[vl];
            op[vl] = fill;
            PROC(vl, cr, fr, gr);
        }
    }
    // threads whose whole range stayed in batchA move their acc to the A slot
    if (batchB != batchA && cb == batchA) { FLUSH_A(); }
    // whatever remains belongs to batchB (identity if nothing)
    sBs[t] = sum; sBfk[t] = fk; sBfi[t] = fi;
    sB1u[t] = bu; sB1i[t] = bi; sB1c[t] = bc;
    __syncthreads();

    reduce_set(sAs, sAfk, sAfi, sA1u, sA1i, sA1c, sA2u, sA2i, sA2c, t);
    reduce_set(sBs, sBfk, sBfi, sB1u, sB1i, sB1c, sB2u, sB2i, sB2c, t);

    __shared__ bool is_last;
    if (t == 0) {
        int s0 = 2*blk, s1 = 2*blk + 1;
        g_sum[s0] = sAs[0]; g_gfk[s0] = sAfk[0]; g_gfi[s0] = sAfi[0];
        g_g1u[s0] = sA1u[0]; g_g1i[s0] = sA1i[0]; g_g1c[s0] = sA1c[0];
        g_g2u[s0] = sA2u[0]; g_g2i[s0] = sA2i[0]; g_g2c[s0] = sA2c[0];
        g_sbatch[s0] = batchA;
        g_sum[s1] = sBs[0]; g_gfk[s1] = sBfk[0]; g_gfi[s1] = sBfi[0];
        g_g1u[s1] = sB1u[0]; g_g1i[s1] = sB1i[0]; g_g1c[s1] = sB1c[0];
        g_g2u[s1] = sB2u[0]; g_g2i[s1] = sB2i[0]; g_g2c[s1] = sB2c[0];
        g_sbatch[s1] = batchB;
        __threadfence();                           // publish partials + fill stores
        unsigned int v = atomicAdd(&g_ctr, 1u);
        is_last = (v == (unsigned)(GRID - 1));
    }
    __syncthreads();
    if (!is_last) return;

    // ---- last block: finalize all batches (one thread per batch) ----
    if (t == 0) g_ctr = 0;                         // reset for next graph replay
    if (t >= BATCH) return;
    int bb = t;
    int X  = bb * B4;                              // first float4 of batch
    int X2 = X + B4 - 1;                           // last float4 of batch

    int k1 = min(X / QF, GRID - 1);
    while (k1 > 0 && blk_start(k1) > X) --k1;
    while (k1 < GRID - 1 && blk_start(k1 + 1) <= X) ++k1;
    int k2 = min(X2 / QF, GRID - 1);
    while (k2 > 0 && blk_start(k2) > X2) --k2;
    while (k2 < GRID - 1 && blk_start(k2 + 1) <= X2) ++k2;

    float S = 0.f;
    for (int kk = k1; kk <= k2; ++kk)
        for (int w = 0; w < 2; ++w) {
            int s = 2*kk + w;
            if (g_sbatch[s] == bb) S += g_sum[s];
        }
    float invS = 1.0f / S;

    float ffk = NEGINF; int ffi = IDENT_I;
    float bsc = NEGINF; int bbi = IDENT_I;
    for (int kk = k1; kk <= k2; ++kk)
        for (int w = 0; w < 2; ++w) {
            int s = 2*kk + w;
            if (g_sbatch[s] != bb) continue;
            if (better(g_gfk[s], g_gfi[s], ffk, ffi)) { ffk = g_gfk[s]; ffi = g_gfi[s]; }
            #pragma unroll
            for (int w2 = 0; w2 < 2; ++w2) {
                float u   = w2 ? g_g2u[s] : g_g1u[s];
                int   idx = w2 ? g_g2i[s] : g_g1i[s];
                float cm  = w2 ? g_g2c[s] : g_g1c[s];
                if (idx == IDENT_I) continue;
                float uc = fmaxf(u, 1e-12f);
                float gmb = -logf(-logf(uc));      // exact reference gumbel
                float p = (cm + 1e-6f) * invS;
                float sc = log1pf(-p) + gmb;       // exact reference bg score
                if (better(sc, idx, bsc, bbi)) { bsc = sc; bbi = idx; }
            }
        }

    int fr = (ffi >> 9) & 511, fc = ffi & 511;
    int br = (bbi >> 9) & 511, bc2 = bbi & 511;
    // note: ffi/bbi are global element indices; row within image = (idx % HW) >> 9.
    // idx % HW == idx & (HW-1); (idx & 0x3FFFF) >> 9 == (idx >> 9) & 511 ✓
    float* o = out + (size_t)bb*HW;
    #pragma unroll
    for (int dr = -1; dr <= 1; ++dr) {
        #pragma unroll
        for (int dc = -1; dc <= 1; ++dc) {
            int r = fr + dr, cq = fc + dc;
            if (r >= 0 && r < HDIM && cq >= 0 && cq < WDIM &&
                !(abs(r - br) <= 1 && abs(cq - bc2) <= 1))
                o[r*WDIM + cq] = 1.0f;
            r = br + dr; cq = bc2 + dc;
            if (r >= 0 && r < HDIM && cq >= 0 && cq < WDIM &&
                !(abs(r - fr) <= 1 && abs(cq - fc) <= 1))
                o[r*WDIM + cq] = 0.0f;
        }
    }
}

extern "C" void kernel_launch(void* const* d_in, const int* in_sizes, int n_in,
                              void* d_out, int out_size) {
    const float* x   = (const float*)d_in[0];
    const float* ufg = (const float*)d_in[1];
    const float* ubg = (const float*)d_in[2];
    float* out = (float*)d_out;
    k_all<<<GRID, NT>>>(x, ufg, ubg, out);
}